// round 12
// baseline (speedup 1.0000x reference)
#include <cuda_runtime.h>
#include <cstdint>

// DecoderLSTM on B200: batch dimension is degenerate (features unused, x0=0,
// shared weights) -> ONE 84-step 2-layer LSTM (H=512) computed cooperatively
// by 128 persistent CTAs. R12 = R6 (272us) with exactly one change: L1's
// Whh1@h1(t-1) matvec is hoisted into the idle tail AFTER the x-publish
// barrier, halving L1's on-path matvec (32 -> 16 iterations) without
// lengthening the projection/x path. Exchanges: tagged u64 words, 8x
// replicated, nanosleep(64) backoff. Finally points[84][3] is broadcast into
// out[16384][84][3] masked by seq_lengths.

#define NCTA   128
#define NT     256
#define HDIM   512
#define TSTEPS 84
#define BROWS  128     // batch rows per CTA
#define NREP   8       // post replication factor

typedef unsigned long long u64t;
typedef unsigned int u32t;

// Tagged posts: upper 32 = monotonic version tag, lower 32 = float bits.
// 8B-aligned relaxed accesses are single-copy atomic -> tag+payload travel
// together. Never reset: each run reads its own CTA's words at entry as the
// tag base (equal across runs/replicas by construction) -> graph replays are
// deterministic. Replica r is a separate 4KB array so different replicas hit
// different L2 slice sets.
__device__ u64t g_P0[NREP][2][HDIM];   // layer-0 h posts
__device__ u64t g_P1[NREP][2][HDIM];   // layer-1 h posts

static __device__ __forceinline__ void post64(u64t* p, u32t tag, float h) {
    u64t v = ((u64t)tag << 32) | (u64t)__float_as_uint(h);
    asm volatile("st.relaxed.gpu.global.u64 [%0], %1;" :: "l"(p), "l"(v) : "memory");
}
static __device__ __forceinline__ u64t ldrel(const u64t* p) {
    u64t v;
    asm volatile("ld.relaxed.gpu.global.u64 %0, [%1];" : "=l"(v) : "l"(p) : "memory");
    return v;
}
__device__ __forceinline__ float sigm(float z)  { return 1.0f / (1.0f + __expf(-z)); }
__device__ __forceinline__ float tanh_(float z) { return 2.0f / (1.0f + __expf(-2.0f * z)) - 1.0f; }

#define BARS(id, n) asm volatile("bar.sync %0, %1;" :: "r"(id), "r"(n) : "memory")

// Poll 4 tagged words (warp-coalesced stride-128 layout) with nanosleep
// backoff, stage floats to smem.
static __device__ __forceinline__ void poll4(const u64t* arr, int k, u32t tag, float* dst) {
    u64t v0, v1, v2, v3;
    for (;;) {
        v0 = ldrel(arr + k);
        v1 = ldrel(arr + k + 128);
        v2 = ldrel(arr + k + 256);
        v3 = ldrel(arr + k + 384);
        bool ok = ((u32t)(v0 >> 32) == tag) & ((u32t)(v1 >> 32) == tag) &
                  ((u32t)(v2 >> 32) == tag) & ((u32t)(v3 >> 32) == tag);
        if (ok) break;
        __nanosleep(64);
    }
    dst[k]       = __uint_as_float((u32t)v0);
    dst[k + 128] = __uint_as_float((u32t)v1);
    dst[k + 256] = __uint_as_float((u32t)v2);
    dst[k + 384] = __uint_as_float((u32t)v3);
}

__global__ void __launch_bounds__(NT, 1)
lstm_persistent_kernel(const int* __restrict__ seq,
                       const float* __restrict__ Wih0, const float* __restrict__ Whh0,
                       const float* __restrict__ bih0, const float* __restrict__ bhh0,
                       const float* __restrict__ Wih1, const float* __restrict__ Whh1,
                       const float* __restrict__ bih1, const float* __restrict__ bhh1,
                       const float* __restrict__ Wpc,  const float* __restrict__ bpc,
                       float* __restrict__ out)
{
    __shared__ float h0s[2][HDIM];
    __shared__ float h1s[2][HDIM];
    __shared__ float pts[TSTEPS * 3];
    __shared__ u32t  sbase[4];      // tag bases: P0 par0/par1, P1 par0/par1

    const int tid  = threadIdx.x;
    const int w    = tid >> 5;
    const int lane = tid & 31;
    const int cta  = blockIdx.x;
    const int rep  = cta & (NREP - 1);   // which replica this CTA polls

    for (int i = tid; i < HDIM; i += NT) {
        h0s[0][i] = 0.0f; h0s[1][i] = 0.0f;
        h1s[0][i] = 0.0f; h1s[1][i] = 0.0f;
    }
    if (tid == 0) {
        // Read tag bases from OWN CTA's words (replica 0) before posting
        // anything; no race (other CTAs never write these words).
        sbase[0] = (u32t)(ldrel(&g_P0[0][0][4 * cta]) >> 32);
        sbase[1] = (u32t)(ldrel(&g_P0[0][1][4 * cta]) >> 32);
        sbase[2] = (u32t)(ldrel(&g_P1[0][0][4 * cta]) >> 32);
        sbase[3] = (u32t)(ldrel(&g_P1[0][1][4 * cta]) >> 32);
    }
    __syncthreads();

    if (w < 4) {
        // ================= layer 0: warp w owns hidden unit 4*cta + w ========
        float whh0r[4][16];
        #pragma unroll
        for (int g = 0; g < 4; g++) {
            const float* p = Whh0 + (size_t)(g * HDIM + 4 * cta + w) * HDIM + lane;
            #pragma unroll
            for (int m = 0; m < 16; m++) whh0r[g][m] = p[32 * m];
        }
        float wx[4][3], bz[4];
        if (lane == 0) {
            #pragma unroll
            for (int g = 0; g < 4; g++) {
                int row = g * HDIM + 4 * cta + w;
                wx[g][0] = Wih0[row * 3];
                wx[g][1] = Wih0[row * 3 + 1];
                wx[g][2] = Wih0[row * 3 + 2];
                bz[g] = bih0[row] + bhh0[row];
            }
        }
        float c0 = 0.0f;
        float a0 = 0.f, a1 = 0.f, a2 = 0.f, a3 = 0.f;  // whh0 @ h0(t-1) partials
        const int k = tid;  // 0..127

        for (int t = 0; t < TSTEPS; t++) {
            const int par = t & 1;
            const u32t tg0 = sbase[par]     + (u32t)(t >> 1) + 1u;
            const u32t tg1 = sbase[2 + par] + (u32t)(t >> 1) + 1u;
            // reduce gate partials
            #pragma unroll
            for (int off = 16; off; off >>= 1) {
                a0 += __shfl_xor_sync(0xffffffffu, a0, off);
                a1 += __shfl_xor_sync(0xffffffffu, a1, off);
                a2 += __shfl_xor_sync(0xffffffffu, a2, off);
                a3 += __shfl_xor_sync(0xffffffffu, a3, off);
            }
            if (t > 0) BARS(1, 224);        // wait x(t) = pts[t-1] from proj warps
            float hval = 0.0f;
            if (lane == 0) {
                float x0 = 0.f, x1 = 0.f, x2 = 0.f;
                if (t > 0) { x0 = pts[3 * t - 3]; x1 = pts[3 * t - 2]; x2 = pts[3 * t - 1]; }
                float zi = a0 + bz[0] + wx[0][0] * x0 + wx[0][1] * x1 + wx[0][2] * x2;
                float zf = a1 + bz[1] + wx[1][0] * x0 + wx[1][1] * x1 + wx[1][2] * x2;
                float zg = a2 + bz[2] + wx[2][0] * x0 + wx[2][1] * x1 + wx[2][2] * x2;
                float zo = a3 + bz[3] + wx[3][0] * x0 + wx[3][1] * x1 + wx[3][2] * x2;
                c0 = sigm(zf) * c0 + sigm(zi) * tanh_(zg);
                hval = sigm(zo) * tanh_(c0);
            }
            hval = __shfl_sync(0xffffffffu, hval, 0);
            if (lane < NREP)                 // post to all replicas in parallel
                post64(&g_P0[lane][par][4 * cta + w], tg0, hval);
            // poll h1(t) from this CTA's replica (hidden under layer-1 compute)
            poll4(g_P1[rep][par], k, tg1, h1s[par]);
            BARS(3, 256);                   // h1s[par] + h0s[par] visible to all
            // precompute whh0 @ h0(t) for next step (overlaps with projection)
            a0 = a1 = a2 = a3 = 0.0f;
            const float* hs = h0s[par];
            #pragma unroll
            for (int m = 0; m < 16; m++) {
                float h = hs[lane + 32 * m];
                a0 += whh0r[0][m] * h;
                a1 += whh0r[1][m] * h;
                a2 += whh0r[2][m] * h;
                a3 += whh0r[3][m] * h;
            }
        }
    } else {
        // ====== layer 1: warp 4+u owns unit 4*cta+u; warps 4-6 also project ==
        const int u = w - 4;
        float wih1r[4][16], whh1r[4][16];
        #pragma unroll
        for (int g = 0; g < 4; g++) {
            const float* p1 = Wih1 + (size_t)(g * HDIM + 4 * cta + u) * HDIM + lane;
            const float* p2 = Whh1 + (size_t)(g * HDIM + 4 * cta + u) * HDIM + lane;
            #pragma unroll
            for (int m = 0; m < 16; m++) { wih1r[g][m] = p1[32 * m]; whh1r[g][m] = p2[32 * m]; }
        }
        float wpcr[16];
        float bpcv = 0.0f;
        if (u < 3) {
            const float* p = Wpc + (size_t)u * HDIM + lane;
            #pragma unroll
            for (int m = 0; m < 16; m++) wpcr[m] = p[32 * m];
            if (lane == 0) bpcv = bpc[u];
        }
        float bz[4];
        if (lane == 0) {
            #pragma unroll
            for (int g = 0; g < 4; g++) {
                int row = g * HDIM + 4 * cta + u;
                bz[g] = bih1[row] + bhh1[row];
            }
        }
        float c1 = 0.0f;
        // Whh1 @ h1(t-1) partials, computed in the idle tail of step t-1.
        float bh0 = 0.f, bh1v = 0.f, bh2 = 0.f, bh3 = 0.f;  // zeros at t=0
        const int k = tid - 128;  // 0..127

        for (int t = 0; t < TSTEPS; t++) {
            const int par = t & 1;
            const u32t tg0 = sbase[par]     + (u32t)(t >> 1) + 1u;
            const u32t tg1 = sbase[2 + par] + (u32t)(t >> 1) + 1u;
            // poll h0(t) from this CTA's replica (hidden under layer-0 compute)
            poll4(g_P0[rep][par], k, tg0, h0s[par]);
            BARS(2, 128);                   // h0s[par] complete within group
            // on-path matvec: only Wih1@h0(t); Whh1@h1(t-1) already in bh*
            float a0 = bh0, a1 = bh1v, a2 = bh2, a3 = bh3;
            const float* hn = h0s[par];
            #pragma unroll
            for (int m = 0; m < 16; m++) {
                float x = hn[lane + 32 * m];
                a0 += wih1r[0][m] * x;
                a1 += wih1r[1][m] * x;
                a2 += wih1r[2][m] * x;
                a3 += wih1r[3][m] * x;
            }
            #pragma unroll
            for (int off = 16; off; off >>= 1) {
                a0 += __shfl_xor_sync(0xffffffffu, a0, off);
                a1 += __shfl_xor_sync(0xffffffffu, a1, off);
                a2 += __shfl_xor_sync(0xffffffffu, a2, off);
                a3 += __shfl_xor_sync(0xffffffffu, a3, off);
            }
            float hval = 0.0f;
            if (lane == 0) {
                float zi = a0 + bz[0];
                float zf = a1 + bz[1];
                float zg = a2 + bz[2];
                float zo = a3 + bz[3];
                c1 = sigm(zf) * c1 + sigm(zi) * tanh_(zg);
                hval = sigm(zo) * tanh_(c1);
            }
            hval = __shfl_sync(0xffffffffu, hval, 0);
            if (lane < NREP)
                post64(&g_P1[lane][par][4 * cta + u], tg1, hval);
            BARS(3, 256);                   // join with layer-0 pollers of h1(t)
            if (u < 3) {
                // projection component u: point(t)[u] = Wpc[u] . h1(t) + bpc[u]
                float s = 0.0f;
                const float* h1p = h1s[par];
                #pragma unroll
                for (int m = 0; m < 16; m++) s += wpcr[m] * h1p[lane + 32 * m];
                #pragma unroll
                for (int off = 16; off; off >>= 1) s += __shfl_xor_sync(0xffffffffu, s, off);
                if (lane == 0) pts[3 * t + u] = s + bpcv;
                if (t < TSTEPS - 1) BARS(1, 224);   // release layer-0 for x(t+1)
            }
            // ---- idle-tail hoist: Whh1 @ h1(t) for next step (off x-path:
            // runs after the release; h1s[par] is stable until step t+2) ----
            bh0 = bh1v = bh2 = bh3 = 0.0f;
            const float* hB = h1s[par];
            #pragma unroll
            for (int m = 0; m < 16; m++) {
                float y = hB[lane + 32 * m];
                bh0  += whh1r[0][m] * y;
                bh1v += whh1r[1][m] * y;
                bh2  += whh1r[2][m] * y;
                bh3  += whh1r[3][m] * y;
            }
        }
    }
    __syncthreads();

    // ---- masked broadcast: out[row][t][j] = (t < seq[row]) ? pts[t][j] : 0 --
    const int row0 = cta * BROWS;
    for (int idx = tid; idx < BROWS * 63; idx += NT) {
        int rl = idx / 63;
        int q  = idx - 63 * rl;
        int row = row0 + rl;
        int L = seq[row];
        int e = 4 * q;
        float4 v;
        v.x = ((e    ) / 3 < L) ? pts[e    ] : 0.0f;
        v.y = ((e + 1) / 3 < L) ? pts[e + 1] : 0.0f;
        v.z = ((e + 2) / 3 < L) ? pts[e + 2] : 0.0f;
        v.w = ((e + 3) / 3 < L) ? pts[e + 3] : 0.0f;
        reinterpret_cast<float4*>(out)[(size_t)row * 63 + q] = v;
    }
}

extern "C" void kernel_launch(void* const* d_in, const int* in_sizes, int n_in,
                              void* d_out, int out_size)
{
    // 0 features (unused), 1 seq_lengths, 2 W_ih0, 3 W_hh0, 4 b_ih0, 5 b_hh0,
    // 6 W_ih1, 7 W_hh1, 8 b_ih1, 9 b_hh1, 10 W_pc, 11 b_pc
    (void)in_sizes; (void)n_in; (void)out_size;
    lstm_persistent_kernel<<<NCTA, NT>>>(
        (const int*)  d_in[1],
        (const float*)d_in[2], (const float*)d_in[3],
        (const float*)d_in[4], (const float*)d_in[5],
        (const float*)d_in[6], (const float*)d_in[7],
        (const float*)d_in[8], (const float*)d_in[9],
        (const float*)d_in[10], (const float*)d_in[11],
        (float*)d_out);
}

// round 13
// speedup vs baseline: 1.1046x; 1.1046x over previous
#include <cuda_runtime.h>
#include <cstdint>

// DecoderLSTM on B200: batch dimension is degenerate (features unused, x0=0,
// shared weights) -> ONE 84-step 2-layer LSTM (H=512) computed cooperatively
// by 128 persistent CTAs. R13 = R6 (272us) with exactly one change: the poll
// backoff primitive is a calibrated ~250-cycle clock64 busy-delay instead of
// __nanosleep(64) (whose real quantum may be ~us-scale and would dominate
// the per-step critical path). Retry traffic stays ~30x below pure spin (the
// delay loop is pure ALU, no LSU/LTS pressure). Exchanges: tagged u64 words
// (tag|payload single-copy atomic), 8x replicated across L2 lines. Finally
// points[84][3] is broadcast into out[16384][84][3] masked by seq_lengths.

#define NCTA   128
#define NT     256
#define HDIM   512
#define TSTEPS 84
#define BROWS  128     // batch rows per CTA
#define NREP   8       // post replication factor
#define PAUSE  250     // backoff delay in cycles

typedef unsigned long long u64t;
typedef unsigned int u32t;

// Tagged posts: upper 32 = monotonic version tag, lower 32 = float bits.
// 8B-aligned relaxed accesses are single-copy atomic -> tag+payload travel
// together. Never reset: each run reads its own CTA's words at entry as the
// tag base (equal across runs/replicas by construction) -> graph replays are
// deterministic. Replica r is a separate 4KB array so different replicas hit
// different L2 slice sets.
__device__ u64t g_P0[NREP][2][HDIM];   // layer-0 h posts
__device__ u64t g_P1[NREP][2][HDIM];   // layer-1 h posts

static __device__ __forceinline__ void post64(u64t* p, u32t tag, float h) {
    u64t v = ((u64t)tag << 32) | (u64t)__float_as_uint(h);
    asm volatile("st.relaxed.gpu.global.u64 [%0], %1;" :: "l"(p), "l"(v) : "memory");
}
static __device__ __forceinline__ u64t ldrel(const u64t* p) {
    u64t v;
    asm volatile("ld.relaxed.gpu.global.u64 %0, [%1];" : "=l"(v) : "l"(p) : "memory");
    return v;
}
__device__ __forceinline__ float sigm(float z)  { return 1.0f / (1.0f + __expf(-z)); }
__device__ __forceinline__ float tanh_(float z) { return 2.0f / (1.0f + __expf(-2.0f * z)) - 1.0f; }

#define BARS(id, n) asm volatile("bar.sync %0, %1;" :: "r"(id), "r"(n) : "memory")

// Bounded busy-delay: pure ALU/SR reads, zero memory traffic, ~n cycles.
static __device__ __forceinline__ void pause_cycles(unsigned n) {
    unsigned long long s = clock64();
    while ((unsigned long long)(clock64() - s) < (unsigned long long)n) { }
}

// Poll 4 tagged words (warp-coalesced stride-128 layout) with clock-delay
// backoff, stage floats to smem.
static __device__ __forceinline__ void poll4(const u64t* arr, int k, u32t tag, float* dst) {
    u64t v0, v1, v2, v3;
    for (;;) {
        v0 = ldrel(arr + k);
        v1 = ldrel(arr + k + 128);
        v2 = ldrel(arr + k + 256);
        v3 = ldrel(arr + k + 384);
        bool ok = ((u32t)(v0 >> 32) == tag) & ((u32t)(v1 >> 32) == tag) &
                  ((u32t)(v2 >> 32) == tag) & ((u32t)(v3 >> 32) == tag);
        if (ok) break;
        pause_cycles(PAUSE);
    }
    dst[k]       = __uint_as_float((u32t)v0);
    dst[k + 128] = __uint_as_float((u32t)v1);
    dst[k + 256] = __uint_as_float((u32t)v2);
    dst[k + 384] = __uint_as_float((u32t)v3);
}

__global__ void __launch_bounds__(NT, 1)
lstm_persistent_kernel(const int* __restrict__ seq,
                       const float* __restrict__ Wih0, const float* __restrict__ Whh0,
                       const float* __restrict__ bih0, const float* __restrict__ bhh0,
                       const float* __restrict__ Wih1, const float* __restrict__ Whh1,
                       const float* __restrict__ bih1, const float* __restrict__ bhh1,
                       const float* __restrict__ Wpc,  const float* __restrict__ bpc,
                       float* __restrict__ out)
{
    __shared__ float h0s[2][HDIM];
    __shared__ float h1s[2][HDIM];
    __shared__ float pts[TSTEPS * 3];
    __shared__ u32t  sbase[4];      // tag bases: P0 par0/par1, P1 par0/par1

    const int tid  = threadIdx.x;
    const int w    = tid >> 5;
    const int lane = tid & 31;
    const int cta  = blockIdx.x;
    const int rep  = cta & (NREP - 1);   // which replica this CTA polls

    for (int i = tid; i < HDIM; i += NT) {
        h0s[0][i] = 0.0f; h0s[1][i] = 0.0f;
        h1s[0][i] = 0.0f; h1s[1][i] = 0.0f;
    }
    if (tid == 0) {
        // Read tag bases from OWN CTA's words (replica 0) before posting
        // anything; no race (other CTAs never write these words).
        sbase[0] = (u32t)(ldrel(&g_P0[0][0][4 * cta]) >> 32);
        sbase[1] = (u32t)(ldrel(&g_P0[0][1][4 * cta]) >> 32);
        sbase[2] = (u32t)(ldrel(&g_P1[0][0][4 * cta]) >> 32);
        sbase[3] = (u32t)(ldrel(&g_P1[0][1][4 * cta]) >> 32);
    }
    __syncthreads();

    if (w < 4) {
        // ================= layer 0: warp w owns hidden unit 4*cta + w ========
        float whh0r[4][16];
        #pragma unroll
        for (int g = 0; g < 4; g++) {
            const float* p = Whh0 + (size_t)(g * HDIM + 4 * cta + w) * HDIM + lane;
            #pragma unroll
            for (int m = 0; m < 16; m++) whh0r[g][m] = p[32 * m];
        }
        float wx[4][3], bz[4];
        if (lane == 0) {
            #pragma unroll
            for (int g = 0; g < 4; g++) {
                int row = g * HDIM + 4 * cta + w;
                wx[g][0] = Wih0[row * 3];
                wx[g][1] = Wih0[row * 3 + 1];
                wx[g][2] = Wih0[row * 3 + 2];
                bz[g] = bih0[row] + bhh0[row];
            }
        }
        float c0 = 0.0f;
        float a0 = 0.f, a1 = 0.f, a2 = 0.f, a3 = 0.f;  // whh0 @ h0(t-1) partials
        const int k = tid;  // 0..127

        for (int t = 0; t < TSTEPS; t++) {
            const int par = t & 1;
            const u32t tg0 = sbase[par]     + (u32t)(t >> 1) + 1u;
            const u32t tg1 = sbase[2 + par] + (u32t)(t >> 1) + 1u;
            // reduce gate partials
            #pragma unroll
            for (int off = 16; off; off >>= 1) {
                a0 += __shfl_xor_sync(0xffffffffu, a0, off);
                a1 += __shfl_xor_sync(0xffffffffu, a1, off);
                a2 += __shfl_xor_sync(0xffffffffu, a2, off);
                a3 += __shfl_xor_sync(0xffffffffu, a3, off);
            }
            if (t > 0) BARS(1, 224);        // wait x(t) = pts[t-1] from proj warps
            float hval = 0.0f;
            if (lane == 0) {
                float x0 = 0.f, x1 = 0.f, x2 = 0.f;
                if (t > 0) { x0 = pts[3 * t - 3]; x1 = pts[3 * t - 2]; x2 = pts[3 * t - 1]; }
                float zi = a0 + bz[0] + wx[0][0] * x0 + wx[0][1] * x1 + wx[0][2] * x2;
                float zf = a1 + bz[1] + wx[1][0] * x0 + wx[1][1] * x1 + wx[1][2] * x2;
                float zg = a2 + bz[2] + wx[2][0] * x0 + wx[2][1] * x1 + wx[2][2] * x2;
                float zo = a3 + bz[3] + wx[3][0] * x0 + wx[3][1] * x1 + wx[3][2] * x2;
                c0 = sigm(zf) * c0 + sigm(zi) * tanh_(zg);
                hval = sigm(zo) * tanh_(c0);
            }
            hval = __shfl_sync(0xffffffffu, hval, 0);
            if (lane < NREP)                 // post to all replicas in parallel
                post64(&g_P0[lane][par][4 * cta + w], tg0, hval);
            // poll h1(t) from this CTA's replica (hidden under layer-1 compute)
            poll4(g_P1[rep][par], k, tg1, h1s[par]);
            BARS(3, 256);                   // h1s[par] + h0s[par] visible to all
            // precompute whh0 @ h0(t) for next step (overlaps with projection)
            a0 = a1 = a2 = a3 = 0.0f;
            const float* hs = h0s[par];
            #pragma unroll
            for (int m = 0; m < 16; m++) {
                float h = hs[lane + 32 * m];
                a0 += whh0r[0][m] * h;
                a1 += whh0r[1][m] * h;
                a2 += whh0r[2][m] * h;
                a3 += whh0r[3][m] * h;
            }
        }
    } else {
        // ====== layer 1: warp 4+u owns unit 4*cta+u; warps 4-6 also project ==
        const int u = w - 4;
        float wih1r[4][16], whh1r[4][16];
        #pragma unroll
        for (int g = 0; g < 4; g++) {
            const float* p1 = Wih1 + (size_t)(g * HDIM + 4 * cta + u) * HDIM + lane;
            const float* p2 = Whh1 + (size_t)(g * HDIM + 4 * cta + u) * HDIM + lane;
            #pragma unroll
            for (int m = 0; m < 16; m++) { wih1r[g][m] = p1[32 * m]; whh1r[g][m] = p2[32 * m]; }
        }
        float wpcr[16];
        float bpcv = 0.0f;
        if (u < 3) {
            const float* p = Wpc + (size_t)u * HDIM + lane;
            #pragma unroll
            for (int m = 0; m < 16; m++) wpcr[m] = p[32 * m];
            if (lane == 0) bpcv = bpc[u];
        }
        float bz[4];
        if (lane == 0) {
            #pragma unroll
            for (int g = 0; g < 4; g++) {
                int row = g * HDIM + 4 * cta + u;
                bz[g] = bih1[row] + bhh1[row];
            }
        }
        float c1 = 0.0f;
        const int k = tid - 128;  // 0..127

        for (int t = 0; t < TSTEPS; t++) {
            const int par = t & 1;
            const u32t tg0 = sbase[par]     + (u32t)(t >> 1) + 1u;
            const u32t tg1 = sbase[2 + par] + (u32t)(t >> 1) + 1u;
            // poll h0(t) from this CTA's replica (hidden under layer-0 compute)
            poll4(g_P0[rep][par], k, tg0, h0s[par]);
            BARS(2, 128);                   // h0s[par] complete within group
            float a0 = 0.f, a1 = 0.f, a2 = 0.f, a3 = 0.f;
            const float* hn = h0s[par];
            const float* hp = h1s[par ^ 1]; // h1(t-1); zeros at t=0
            #pragma unroll
            for (int m = 0; m < 16; m++) {
                float x = hn[lane + 32 * m];
                float y = hp[lane + 32 * m];
                a0 += wih1r[0][m] * x + whh1r[0][m] * y;
                a1 += wih1r[1][m] * x + whh1r[1][m] * y;
                a2 += wih1r[2][m] * x + whh1r[2][m] * y;
                a3 += wih1r[3][m] * x + whh1r[3][m] * y;
            }
            #pragma unroll
            for (int off = 16; off; off >>= 1) {
                a0 += __shfl_xor_sync(0xffffffffu, a0, off);
                a1 += __shfl_xor_sync(0xffffffffu, a1, off);
                a2 += __shfl_xor_sync(0xffffffffu, a2, off);
                a3 += __shfl_xor_sync(0xffffffffu, a3, off);
            }
            float hval = 0.0f;
            if (lane == 0) {
                float zi = a0 + bz[0];
                float zf = a1 + bz[1];
                float zg = a2 + bz[2];
                float zo = a3 + bz[3];
                c1 = sigm(zf) * c1 + sigm(zi) * tanh_(zg);
                hval = sigm(zo) * tanh_(c1);
            }
            hval = __shfl_sync(0xffffffffu, hval, 0);
            if (lane < NREP)
                post64(&g_P1[lane][par][4 * cta + u], tg1, hval);
            BARS(3, 256);                   // join with layer-0 pollers of h1(t)
            if (u < 3) {
                // projection component u: point(t)[u] = Wpc[u] . h1(t) + bpc[u]
                float s = 0.0f;
                const float* h1p = h1s[par];
                #pragma unroll
                for (int m = 0; m < 16; m++) s += wpcr[m] * h1p[lane + 32 * m];
                #pragma unroll
                for (int off = 16; off; off >>= 1) s += __shfl_xor_sync(0xffffffffu, s, off);
                if (lane == 0) pts[3 * t + u] = s + bpcv;
                if (t < TSTEPS - 1) BARS(1, 224);   // release layer-0 for x(t+1)
            }
        }
    }
    __syncthreads();

    // ---- masked broadcast: out[row][t][j] = (t < seq[row]) ? pts[t][j] : 0 --
    const int row0 = cta * BROWS;
    for (int idx = tid; idx < BROWS * 63; idx += NT) {
        int rl = idx / 63;
        int q  = idx - 63 * rl;
        int row = row0 + rl;
        int L = seq[row];
        int e = 4 * q;
        float4 v;
        v.x = ((e    ) / 3 < L) ? pts[e    ] : 0.0f;
        v.y = ((e + 1) / 3 < L) ? pts[e + 1] : 0.0f;
        v.z = ((e + 2) / 3 < L) ? pts[e + 2] : 0.0f;
        v.w = ((e + 3) / 3 < L) ? pts[e + 3] : 0.0f;
        reinterpret_cast<float4*>(out)[(size_t)row * 63 + q] = v;
    }
}

extern "C" void kernel_launch(void* const* d_in, const int* in_sizes, int n_in,
                              void* d_out, int out_size)
{
    // 0 features (unused), 1 seq_lengths, 2 W_ih0, 3 W_hh0, 4 b_ih0, 5 b_hh0,
    // 6 W_ih1, 7 W_hh1, 8 b_ih1, 9 b_hh1, 10 W_pc, 11 b_pc
    (void)in_sizes; (void)n_in; (void)out_size;
    lstm_persistent_kernel<<<NCTA, NT>>>(
        (const int*)  d_in[1],
        (const float*)d_in[2], (const float*)d_in[3],
        (const float*)d_in[4], (const float*)d_in[5],
        (const float*)d_in[6], (const float*)d_in[7],
        (const float*)d_in[8], (const float*)d_in[9],
        (const float*)d_in[10], (const float*)d_in[11],
        (float*)d_out);
}

// round 16
// speedup vs baseline: 1.1980x; 1.0845x over previous
#include <cuda_runtime.h>
#include <cstdint>

// DecoderLSTM on B200: batch dimension is degenerate (features unused, x0=0,
// shared weights) -> ONE 84-step 2-layer LSTM (H=512) computed cooperatively
// by 128 persistent CTAs. Exchanges use tagged 64-bit words (tag|payload in
// one 8B atomic word) replicated 8x across separate L2 lines; poll loops use
// nanosleep backoff so spinning warps don't flood LTS queues / SM issue slots.
// Finally points[84][3] is broadcast into out[16384][84][3] masked by
// seq_lengths.  [R16 = exact resubmission of the verified-best R6 kernel:
// two consecutive broker-side failures require re-validating the
// measurement channel on a known-good source before further experiments.]

#define NCTA   128
#define NT     256
#define HDIM   512
#define TSTEPS 84
#define BROWS  128     // batch rows per CTA
#define NREP   8       // post replication factor

typedef unsigned long long u64t;
typedef unsigned int u32t;

// Tagged posts: upper 32 = monotonic version tag, lower 32 = float bits.
// 8B-aligned relaxed accesses are single-copy atomic -> tag+payload travel
// together. Never reset: each run reads its own CTA's words at entry as the
// tag base (equal across runs/replicas by construction) -> graph replays are
// deterministic. Replica r is a separate 4KB array so different replicas hit
// different L2 slice sets.
__device__ u64t g_P0[NREP][2][HDIM];   // layer-0 h posts
__device__ u64t g_P1[NREP][2][HDIM];   // layer-1 h posts

static __device__ __forceinline__ void post64(u64t* p, u32t tag, float h) {
    u64t v = ((u64t)tag << 32) | (u64t)__float_as_uint(h);
    asm volatile("st.relaxed.gpu.global.u64 [%0], %1;" :: "l"(p), "l"(v) : "memory");
}
static __device__ __forceinline__ u64t ldrel(const u64t* p) {
    u64t v;
    asm volatile("ld.relaxed.gpu.global.u64 %0, [%1];" : "=l"(v) : "l"(p) : "memory");
    return v;
}
__device__ __forceinline__ float sigm(float z)  { return 1.0f / (1.0f + __expf(-z)); }
__device__ __forceinline__ float tanh_(float z) { return 2.0f / (1.0f + __expf(-2.0f * z)) - 1.0f; }

#define BARS(id, n) asm volatile("bar.sync %0, %1;" :: "r"(id), "r"(n) : "memory")

// Poll 4 tagged words (warp-coalesced stride-128 layout) with nanosleep
// backoff, stage floats to smem. Backoff keeps spinning warps from
// saturating the LTS queues (delaying the poster's store visibility) and
// from stealing issue/LSU slots from the computing warps on this SM.
static __device__ __forceinline__ void poll4(const u64t* arr, int k, u32t tag, float* dst) {
    u64t v0, v1, v2, v3;
    for (;;) {
        v0 = ldrel(arr + k);
        v1 = ldrel(arr + k + 128);
        v2 = ldrel(arr + k + 256);
        v3 = ldrel(arr + k + 384);
        bool ok = ((u32t)(v0 >> 32) == tag) & ((u32t)(v1 >> 32) == tag) &
                  ((u32t)(v2 >> 32) == tag) & ((u32t)(v3 >> 32) == tag);
        if (ok) break;
        __nanosleep(64);
    }
    dst[k]       = __uint_as_float((u32t)v0);
    dst[k + 128] = __uint_as_float((u32t)v1);
    dst[k + 256] = __uint_as_float((u32t)v2);
    dst[k + 384] = __uint_as_float((u32t)v3);
}

__global__ void __launch_bounds__(NT, 1)
lstm_persistent_kernel(const int* __restrict__ seq,
                       const float* __restrict__ Wih0, const float* __restrict__ Whh0,
                       const float* __restrict__ bih0, const float* __restrict__ bhh0,
                       const float* __restrict__ Wih1, const float* __restrict__ Whh1,
                       const float* __restrict__ bih1, const float* __restrict__ bhh1,
                       const float* __restrict__ Wpc,  const float* __restrict__ bpc,
                       float* __restrict__ out)
{
    __shared__ float h0s[2][HDIM];
    __shared__ float h1s[2][HDIM];
    __shared__ float pts[TSTEPS * 3];
    __shared__ u32t  sbase[4];      // tag bases: P0 par0/par1, P1 par0/par1

    const int tid  = threadIdx.x;
    const int w    = tid >> 5;
    const int lane = tid & 31;
    const int cta  = blockIdx.x;
    const int rep  = cta & (NREP - 1);   // which replica this CTA polls

    for (int i = tid; i < HDIM; i += NT) {
        h0s[0][i] = 0.0f; h0s[1][i] = 0.0f;
        h1s[0][i] = 0.0f; h1s[1][i] = 0.0f;
    }
    if (tid == 0) {
        // Read tag bases from OWN CTA's words (replica 0) before posting
        // anything; no race (other CTAs never write these words).
        sbase[0] = (u32t)(ldrel(&g_P0[0][0][4 * cta]) >> 32);
        sbase[1] = (u32t)(ldrel(&g_P0[0][1][4 * cta]) >> 32);
        sbase[2] = (u32t)(ldrel(&g_P1[0][0][4 * cta]) >> 32);
        sbase[3] = (u32t)(ldrel(&g_P1[0][1][4 * cta]) >> 32);
    }
    __syncthreads();

    if (w < 4) {
        // ================= layer 0: warp w owns hidden unit 4*cta + w ========
        float whh0r[4][16];
        #pragma unroll
        for (int g = 0; g < 4; g++) {
            const float* p = Whh0 + (size_t)(g * HDIM + 4 * cta + w) * HDIM + lane;
            #pragma unroll
            for (int m = 0; m < 16; m++) whh0r[g][m] = p[32 * m];
        }
        float wx[4][3], bz[4];
        if (lane == 0) {
            #pragma unroll
            for (int g = 0; g < 4; g++) {
                int row = g * HDIM + 4 * cta + w;
                wx[g][0] = Wih0[row * 3];
                wx[g][1] = Wih0[row * 3 + 1];
                wx[g][2] = Wih0[row * 3 + 2];
                bz[g] = bih0[row] + bhh0[row];
            }
        }
        float c0 = 0.0f;
        float a0 = 0.f, a1 = 0.f, a2 = 0.f, a3 = 0.f;  // whh0 @ h0(t-1) partials
        const int k = tid;  // 0..127

        for (int t = 0; t < TSTEPS; t++) {
            const int par = t & 1;
            const u32t tg0 = sbase[par]     + (u32t)(t >> 1) + 1u;
            const u32t tg1 = sbase[2 + par] + (u32t)(t >> 1) + 1u;
            // reduce gate partials
            #pragma unroll
            for (int off = 16; off; off >>= 1) {
                a0 += __shfl_xor_sync(0xffffffffu, a0, off);
                a1 += __shfl_xor_sync(0xffffffffu, a1, off);
                a2 += __shfl_xor_sync(0xffffffffu, a2, off);
                a3 += __shfl_xor_sync(0xffffffffu, a3, off);
            }
            if (t > 0) BARS(1, 224);        // wait x(t) = pts[t-1] from proj warps
            float hval = 0.0f;
            if (lane == 0) {
                float x0 = 0.f, x1 = 0.f, x2 = 0.f;
                if (t > 0) { x0 = pts[3 * t - 3]; x1 = pts[3 * t - 2]; x2 = pts[3 * t - 1]; }
                float zi = a0 + bz[0] + wx[0][0] * x0 + wx[0][1] * x1 + wx[0][2] * x2;
                float zf = a1 + bz[1] + wx[1][0] * x0 + wx[1][1] * x1 + wx[1][2] * x2;
                float zg = a2 + bz[2] + wx[2][0] * x0 + wx[2][1] * x1 + wx[2][2] * x2;
                float zo = a3 + bz[3] + wx[3][0] * x0 + wx[3][1] * x1 + wx[3][2] * x2;
                c0 = sigm(zf) * c0 + sigm(zi) * tanh_(zg);
                hval = sigm(zo) * tanh_(c0);
            }
            hval = __shfl_sync(0xffffffffu, hval, 0);
            if (lane < NREP)                 // post to all replicas in parallel
                post64(&g_P0[lane][par][4 * cta + w], tg0, hval);
            // poll h1(t) from this CTA's replica (hidden under layer-1 compute)
            poll4(g_P1[rep][par], k, tg1, h1s[par]);
            BARS(3, 256);                   // h1s[par] + h0s[par] visible to all
            // precompute whh0 @ h0(t) for next step (overlaps with projection)
            a0 = a1 = a2 = a3 = 0.0f;
            const float* hs = h0s[par];
            #pragma unroll
            for (int m = 0; m < 16; m++) {
                float h = hs[lane + 32 * m];
                a0 += whh0r[0][m] * h;
                a1 += whh0r[1][m] * h;
                a2 += whh0r[2][m] * h;
                a3 += whh0r[3][m] * h;
            }
        }
    } else {
        // ====== layer 1: warp 4+u owns unit 4*cta+u; warps 4-6 also project ==
        const int u = w - 4;
        float wih1r[4][16], whh1r[4][16];
        #pragma unroll
        for (int g = 0; g < 4; g++) {
            const float* p1 = Wih1 + (size_t)(g * HDIM + 4 * cta + u) * HDIM + lane;
            const float* p2 = Whh1 + (size_t)(g * HDIM + 4 * cta + u) * HDIM + lane;
            #pragma unroll
            for (int m = 0; m < 16; m++) { wih1r[g][m] = p1[32 * m]; whh1r[g][m] = p2[32 * m]; }
        }
        float wpcr[16];
        float bpcv = 0.0f;
        if (u < 3) {
            const float* p = Wpc + (size_t)u * HDIM + lane;
            #pragma unroll
            for (int m = 0; m < 16; m++) wpcr[m] = p[32 * m];
            if (lane == 0) bpcv = bpc[u];
        }
        float bz[4];
        if (lane == 0) {
            #pragma unroll
            for (int g = 0; g < 4; g++) {
                int row = g * HDIM + 4 * cta + u;
                bz[g] = bih1[row] + bhh1[row];
            }
        }
        float c1 = 0.0f;
        const int k = tid - 128;  // 0..127

        for (int t = 0; t < TSTEPS; t++) {
            const int par = t & 1;
            const u32t tg0 = sbase[par]     + (u32t)(t >> 1) + 1u;
            const u32t tg1 = sbase[2 + par] + (u32t)(t >> 1) + 1u;
            // poll h0(t) from this CTA's replica (hidden under layer-0 compute)
            poll4(g_P0[rep][par], k, tg0, h0s[par]);
            BARS(2, 128);                   // h0s[par] complete within group
            float a0 = 0.f, a1 = 0.f, a2 = 0.f, a3 = 0.f;
            const float* hn = h0s[par];
            const float* hp = h1s[par ^ 1]; // h1(t-1); zeros at t=0
            #pragma unroll
            for (int m = 0; m < 16; m++) {
                float x = hn[lane + 32 * m];
                float y = hp[lane + 32 * m];
                a0 += wih1r[0][m] * x + whh1r[0][m] * y;
                a1 += wih1r[1][m] * x + whh1r[1][m] * y;
                a2 += wih1r[2][m] * x + whh1r[2][m] * y;
                a3 += wih1r[3][m] * x + whh1r[3][m] * y;
            }
            #pragma unroll
            for (int off = 16; off; off >>= 1) {
                a0 += __shfl_xor_sync(0xffffffffu, a0, off);
                a1 += __shfl_xor_sync(0xffffffffu, a1, off);
                a2 += __shfl_xor_sync(0xffffffffu, a2, off);
                a3 += __shfl_xor_sync(0xffffffffu, a3, off);
            }
            float hval = 0.0f;
            if (lane == 0) {
                float zi = a0 + bz[0];
                float zf = a1 + bz[1];
                float zg = a2 + bz[2];
                float zo = a3 + bz[3];
                c1 = sigm(zf) * c1 + sigm(zi) * tanh_(zg);
                hval = sigm(zo) * tanh_(c1);
            }
            hval = __shfl_sync(0xffffffffu, hval, 0);
            if (lane < NREP)
                post64(&g_P1[lane][par][4 * cta + u], tg1, hval);
            BARS(3, 256);                   // join with layer-0 pollers of h1(t)
            if (u < 3) {
                // projection component u: point(t)[u] = Wpc[u] . h1(t) + bpc[u]
                float s = 0.0f;
                const float* h1p = h1s[par];
                #pragma unroll
                for (int m = 0; m < 16; m++) s += wpcr[m] * h1p[lane + 32 * m];
                #pragma unroll
                for (int off = 16; off; off >>= 1) s += __shfl_xor_sync(0xffffffffu, s, off);
                if (lane == 0) pts[3 * t + u] = s + bpcv;
                if (t < TSTEPS - 1) BARS(1, 224);   // release layer-0 for x(t+1)
            }
        }
    }
    __syncthreads();

    // ---- masked broadcast: out[row][t][j] = (t < seq[row]) ? pts[t][j] : 0 --
    const int row0 = cta * BROWS;
    for (int idx = tid; idx < BROWS * 63; idx += NT) {
        int rl = idx / 63;
        int q  = idx - 63 * rl;
        int row = row0 + rl;
        int L = seq[row];
        int e = 4 * q;
        float4 v;
        v.x = ((e    ) / 3 < L) ? pts[e    ] : 0.0f;
        v.y = ((e + 1) / 3 < L) ? pts[e + 1] : 0.0f;
        v.z = ((e + 2) / 3 < L) ? pts[e + 2] : 0.0f;
        v.w = ((e + 3) / 3 < L) ? pts[e + 3] : 0.0f;
        reinterpret_cast<float4*>(out)[(size_t)row * 63 + q] = v;
    }
}

extern "C" void kernel_launch(void* const* d_in, const int* in_sizes, int n_in,
                              void* d_out, int out_size)
{
    // 0 features (unused), 1 seq_lengths, 2 W_ih0, 3 W_hh0, 4 b_ih0, 5 b_hh0,
    // 6 W_ih1, 7 W_hh1, 8 b_ih1, 9 b_hh1, 10 W_pc, 11 b_pc
    (void)in_sizes; (void)n_in; (void)out_size;
    lstm_persistent_kernel<<<NCTA, NT>>>(
        (const int*)  d_in[1],
        (const float*)d_in[2], (const float*)d_in[3],
        (const float*)d_in[4], (const float*)d_in[5],
        (const float*)d_in[6], (const float*)d_in[7],
        (const float*)d_in[8], (const float*)d_in[9],
        (const float*)d_in[10], (const float*)d_in[11],
        (float*)d_out);
}